// round 16
// baseline (speedup 1.0000x reference)
#include <cuda_runtime.h>
#include <cuda_fp16.h>

// LSTM: B=4096, T=512, I=10, H=32, O=1. Gate order i,f,g,o.
// R16 = R15 (fp16 gate GEMV: __half2 weights in regs, HFMA2 rt=2, h/x
// broadcast as fp16 in smem, split-bias accumulator init, fp32 activations
// via MUFU.TANH with sigmoid(x)=0.5+0.5*tanh(x/2) folded into 0.5-scaled
// i/f/o weights, fp32 c/h state) with a DENSER one-wave grid:
//   1136 NB=3 blocks + 344 NB=2 blocks = 1480 = 148*10 (exact, no tail)
//   -> 10 blocks/SM, 2.5 warps/SMSP (vs R15's 2.0).
// fp16-NB3 register demand ~180 fits the bound-10 cap (204) with headroom
// (the fp32-NB3 builds spilled because their demand was ~250).

#define B_TOT 4096
#define T_LEN 512
#define I_DIM 10
#define H_DIM 32
#define XSTRIDE (T_LEN * I_DIM)   // 5120
#define NB3_BLOCKS 1136
#define NB2_BLOCKS 344
#define GRID_SZ (NB3_BLOCKS + NB2_BLOCKS)   // 1480 = 148*10

#define SH (0.5f)   // pre-scale for sigmoid gates (i, f, o)

union U16H { uint4 u; __half2 h[4]; };        // 16B <-> 4x half2
union U16L { ulonglong2 u; __half2 h[4]; };   // 16B <-> 4x half2

__device__ __forceinline__ float tanhm(float x) {
    float y; asm("tanh.approx.f32 %0, %1;" : "=f"(y) : "f"(x)); return y;
}
// Pre-scaled sigmoid: input already = x/2. sig(x) = 0.5 + 0.5*tanh(x/2).
__device__ __forceinline__ float sig_half(float y) {
    return fmaf(0.5f, tanhm(y), 0.5f);
}
// Bias split: (f16(b), f16(b - f16(b))) so lo+hi reconstructs b in fp32.
__device__ __forceinline__ __half2 bias_split(float b) {
    const __half hi = __float2half_rn(b);
    const float resid = b - __half2float(hi);
    return __halves2half2(hi, __float2half_rn(resid));
}
__device__ __forceinline__ float hsum2f(__half2 a) {
    const float2 v = __half22float2(a);
    return v.x + v.y;
}

template<int NBk>
__device__ __forceinline__ void lstm_run(
    int lane, int b0,
    const __half2 (&whi)[16], const __half2 (&whf)[16],
    const __half2 (&whg)[16], const __half2 (&who)[16],
    __half2 bp_i, __half2 bp_f, __half2 bp_g, __half2 bp_o,
    const ulonglong2 (*sWx16)[32],
    __half (*sH16)[H_DIM], __half (*sX16)[16],
    const float* __restrict__ x,
    const float* __restrict__ Wd, const float* __restrict__ bd,
    float* __restrict__ out)
{
    float h[NBk], c[NBk], xv[NBk];
#pragma unroll
    for (int k = 0; k < NBk; k++) { h[k] = 0.0f; c[k] = 0.0f; xv[k] = 0.0f; }

    const float* xb = x + b0 * XSTRIDE + lane;
    if (lane < I_DIM) {
#pragma unroll
        for (int k = 0; k < NBk; k++) xv[k] = xb[k * XSTRIDE];   // x(0)
    }
    int toff = I_DIM;   // element offset of x(t+1)

    for (int t = 0; t < T_LEN; t++) {
        // Publish h and x as fp16.
#pragma unroll
        for (int k = 0; k < NBk; k++) sH16[k][lane] = __float2half_rn(h[k]);
        if (lane < I_DIM) {
#pragma unroll
            for (int k = 0; k < NBk; k++) sX16[k][lane] = __float2half_rn(xv[k]);
        }
        __syncwarp();

        // Prefetch next timestep's x (clamped; overlaps gate compute).
        if (lane < I_DIM) {
#pragma unroll
            for (int k = 0; k < NBk; k++) xv[k] = xb[k * XSTRIDE + toff];
        }
        toff = min(toff + I_DIM, XSTRIDE - I_DIM);

        __half2 ai[NBk], af[NBk], ag[NBk], ao[NBk];

        // q = 0 chunk peeled: bias split enters as the HFMA2 addend.
#pragma unroll
        for (int k = 0; k < NBk; k++) {
            U16H r; r.u = *(const uint4*)&sH16[k][0];   // h[0..7] as 4x half2
            ai[k] = __hfma2(whi[0], r.h[0], bp_i);
            af[k] = __hfma2(whf[0], r.h[0], bp_f);
            ag[k] = __hfma2(whg[0], r.h[0], bp_g);
            ao[k] = __hfma2(who[0], r.h[0], bp_o);
#pragma unroll
            for (int j = 1; j < 4; j++) {
                ai[k] = __hfma2(whi[j], r.h[j], ai[k]);
                af[k] = __hfma2(whf[j], r.h[j], af[k]);
                ag[k] = __hfma2(whg[j], r.h[j], ag[k]);
                ao[k] = __hfma2(who[j], r.h[j], ao[k]);
            }
        }
        // Remaining recurrent chunks: q = 1..3 (h[8q .. 8q+7]).
#pragma unroll
        for (int q = 1; q < 4; q++) {
#pragma unroll
            for (int k = 0; k < NBk; k++) {
                U16H r; r.u = *(const uint4*)&sH16[k][8 * q];
#pragma unroll
                for (int j = 0; j < 4; j++) {
                    ai[k] = __hfma2(whi[4 * q + j], r.h[j], ai[k]);
                    af[k] = __hfma2(whf[4 * q + j], r.h[j], af[k]);
                    ag[k] = __hfma2(whg[4 * q + j], r.h[j], ag[k]);
                    ao[k] = __hfma2(who[4 * q + j], r.h[j], ao[k]);
                }
            }
        }
        // Input part: p-outer; one LDS.128 yields all 4 gates' weight pairs.
#pragma unroll
        for (int p = 0; p < 5; p++) {
            U16L w; w.u = sWx16[p][lane];   // h[0]=i, h[1]=f, h[2]=g, h[3]=o
#pragma unroll
            for (int k = 0; k < NBk; k++) {
                const __half2 xq = *(const __half2*)&sX16[k][2 * p];
                ai[k] = __hfma2(w.h[0], xq, ai[k]);
                af[k] = __hfma2(w.h[1], xq, af[k]);
                ag[k] = __hfma2(w.h[2], xq, ag[k]);
                ao[k] = __hfma2(w.h[3], xq, ao[k]);
            }
        }

        // Activations (fp32, MUFU.TANH) + state update.
#pragma unroll
        for (int k = 0; k < NBk; k++) {
            const float gg = tanhm(hsum2f(ag[k]));
            const float gf = sig_half(hsum2f(af[k]));
            const float gi = sig_half(hsum2f(ai[k]));
            const float go = sig_half(hsum2f(ao[k]));
            c[k] = fmaf(gf, c[k], gi * gg);
            h[k] = go * tanhm(c[k]);
        }
        __syncwarp();
    }

    // Final dense (fp32): out[b] = sum_l h[b][l] * Wd[l] + bd
    const float wd = Wd[lane];
    const float bdv = bd[0];
#pragma unroll
    for (int k = 0; k < NBk; k++) {
        float p = h[k] * wd;
#pragma unroll
        for (int off = 16; off; off >>= 1)
            p += __shfl_xor_sync(0xffffffffu, p, off);
        if (lane == 0) out[b0 + k] = p + bdv;
    }
}

__global__ __launch_bounds__(32, 10) void lstm_r16_kernel(
    const float* __restrict__ x,    // [B, T, I]
    const float* __restrict__ Wih,  // [4H, I]
    const float* __restrict__ Whh,  // [4H, H]
    const float* __restrict__ bih,  // [4H]
    const float* __restrict__ bhh,  // [4H]
    const float* __restrict__ Wd,   // [1, H]
    const float* __restrict__ bd,   // [1]
    float* __restrict__ out)        // [B, 1]
{
    __shared__ ulonglong2 sWx16[5][32];                 // fp16 x-weights
    __shared__ __align__(16) __half sH16[3][H_DIM];     // fp16 h broadcast
    __shared__ __align__(16) __half sX16[3][16];        // fp16 x broadcast

    const int lane = threadIdx.x;
    const int bid = blockIdx.x;

    // ---- Recurrent weights into registers as fp16x2 j-pairs.
    // i,f,o rows scaled by 0.5 (sigmoid-via-tanh); g row unscaled.
    __half2 whi[16], whf[16], whg[16], who[16];
#pragma unroll
    for (int p = 0; p < 16; p++) {
        const float* r0 = &Whh[(0 * 32 + lane) * H_DIM + 2 * p];
        const float* r1 = &Whh[(1 * 32 + lane) * H_DIM + 2 * p];
        const float* r2 = &Whh[(2 * 32 + lane) * H_DIM + 2 * p];
        const float* r3 = &Whh[(3 * 32 + lane) * H_DIM + 2 * p];
        whi[p] = __floats2half2_rn(SH * r0[0], SH * r0[1]);
        whf[p] = __floats2half2_rn(SH * r1[0], SH * r1[1]);
        whg[p] = __floats2half2_rn(r2[0], r2[1]);
        who[p] = __floats2half2_rn(SH * r3[0], SH * r3[1]);
    }
    // x-weights into smem: per (p, lane) one 16B = 4 gates' __half2 pairs.
#pragma unroll
    for (int p = 0; p < 5; p++) {
        U16L w;
        w.h[0] = __floats2half2_rn(SH * Wih[(0 * 32 + lane) * I_DIM + 2 * p],
                                   SH * Wih[(0 * 32 + lane) * I_DIM + 2 * p + 1]);
        w.h[1] = __floats2half2_rn(SH * Wih[(1 * 32 + lane) * I_DIM + 2 * p],
                                   SH * Wih[(1 * 32 + lane) * I_DIM + 2 * p + 1]);
        w.h[2] = __floats2half2_rn(Wih[(2 * 32 + lane) * I_DIM + 2 * p],
                                   Wih[(2 * 32 + lane) * I_DIM + 2 * p + 1]);
        w.h[3] = __floats2half2_rn(SH * Wih[(3 * 32 + lane) * I_DIM + 2 * p],
                                   SH * Wih[(3 * 32 + lane) * I_DIM + 2 * p + 1]);
        sWx16[p][lane] = w.u;
    }
    // Bias (scaled for sigmoid gates), split across accumulator halves.
    const __half2 bp_i = bias_split(SH * (bih[0 * 32 + lane] + bhh[0 * 32 + lane]));
    const __half2 bp_f = bias_split(SH * (bih[1 * 32 + lane] + bhh[1 * 32 + lane]));
    const __half2 bp_g = bias_split(bih[2 * 32 + lane] + bhh[2 * 32 + lane]);
    const __half2 bp_o = bias_split(SH * (bih[3 * 32 + lane] + bhh[3 * 32 + lane]));
    __syncwarp();

    if (bid < NB3_BLOCKS) {
        lstm_run<3>(lane, 3 * bid,
                    whi, whf, whg, who, bp_i, bp_f, bp_g, bp_o,
                    sWx16, sH16, sX16, x, Wd, bd, out);
    } else {
        lstm_run<2>(lane, NB3_BLOCKS * 3 + 2 * (bid - NB3_BLOCKS),
                    whi, whf, whg, who, bp_i, bp_f, bp_g, bp_o,
                    sWx16, sH16, sX16, x, Wd, bd, out);
    }
}

extern "C" void kernel_launch(void* const* d_in, const int* in_sizes, int n_in,
                              void* d_out, int out_size) {
    const float* x   = (const float*)d_in[0];
    const float* Wih = (const float*)d_in[1];
    const float* Whh = (const float*)d_in[2];
    const float* bih = (const float*)d_in[3];
    const float* bhh = (const float*)d_in[4];
    const float* Wd  = (const float*)d_in[5];
    const float* bd  = (const float*)d_in[6];
    (void)in_sizes; (void)n_in; (void)out_size;

    lstm_r16_kernel<<<GRID_SZ, 32>>>(x, Wih, Whh, bih, bhh, Wd, bd,
                                     (float*)d_out);
}

// round 17
// speedup vs baseline: 1.2271x; 1.2271x over previous
#include <cuda_runtime.h>
#include <cuda_fp16.h>

// LSTM: B=4096, T=512, I=10, H=32, O=1. Gate order i,f,g,o.
// R17 = R15 (fp16 gate GEMV: __half2 weights in regs, HFMA2 rt=2, h/x
// broadcast fp16 in smem, split-bias accumulator init, mixed 544xNB4 +
// 640xNB3 = 1184 = 148*8 one-wave grid) with two per-step cost cuts:
//  1. Paired activations via tanh.approx.f16x2: (i,f) and (g,o) preact sums
//     packed with lows/highs+HADD2 (alu pipe), one MUFU per PAIR, sigmoid/
//     tanh selection by one HFMA2 with constants (1,.5)/(0,.5).
//     MUFU ops 5->3 per batch; activation chain ~30 cyc shorter.
//  2. Vectorized x reads: LDS.128+LDS.32 per batch (13 LDS/step vs 25).
// c/h state remain fp32. Everything else identical to R15.

#define B_TOT 4096
#define T_LEN 512
#define I_DIM 10
#define H_DIM 32
#define XSTRIDE (T_LEN * I_DIM)   // 5120
#define NB4_BLOCKS 544
#define NB3_BLOCKS 640
#define GRID_SZ (NB4_BLOCKS + NB3_BLOCKS)   // 1184 = 148*8

#define SH (0.5f)   // pre-scale for sigmoid gates (i, f, o)

union U16H { uint4 u; __half2 h[4]; };        // 16B <-> 4x half2
union U16L { ulonglong2 u; __half2 h[4]; };   // 16B <-> 4x half2

__device__ __forceinline__ float tanhm(float x) {
    float y; asm("tanh.approx.f32 %0, %1;" : "=f"(y) : "f"(x)); return y;
}
__device__ __forceinline__ __half2 tanh2(__half2 x) {
    unsigned xu = *reinterpret_cast<unsigned*>(&x);
    unsigned yu;
    asm("tanh.approx.f16x2 %0, %1;" : "=r"(yu) : "r"(xu));
    return *reinterpret_cast<__half2*>(&yu);
}
// Bias split: (f16(b), f16(b - f16(b))) so lo+hi reconstructs b accurately.
__device__ __forceinline__ __half2 bias_split(float b) {
    const __half hi = __float2half_rn(b);
    const float resid = b - __half2float(hi);
    return __halves2half2(hi, __float2half_rn(resid));
}

template<int NBk>
__device__ __forceinline__ void lstm_run(
    int lane, int b0,
    const __half2 (&whi)[16], const __half2 (&whf)[16],
    const __half2 (&whg)[16], const __half2 (&who)[16],
    __half2 bp_i, __half2 bp_f, __half2 bp_g, __half2 bp_o,
    const ulonglong2 (*sWx16)[32],
    __half (*sH16)[H_DIM], __half (*sX16)[16],
    const float* __restrict__ x,
    const float* __restrict__ Wd, const float* __restrict__ bd,
    float* __restrict__ out)
{
    // Activation-selection constants (uniform).
    const __half2 k_05_05 = __floats2half2_rn(0.5f, 0.5f);
    const __half2 k_10_05 = __floats2half2_rn(1.0f, 0.5f);
    const __half2 k_00_05 = __floats2half2_rn(0.0f, 0.5f);

    float h[NBk], c[NBk], xv[NBk];
#pragma unroll
    for (int k = 0; k < NBk; k++) { h[k] = 0.0f; c[k] = 0.0f; xv[k] = 0.0f; }

    const float* xb = x + b0 * XSTRIDE + lane;
    if (lane < I_DIM) {
#pragma unroll
        for (int k = 0; k < NBk; k++) xv[k] = xb[k * XSTRIDE];   // x(0)
    }
    int toff = I_DIM;   // element offset of x(t+1)

    for (int t = 0; t < T_LEN; t++) {
        // Publish h and x as fp16.
#pragma unroll
        for (int k = 0; k < NBk; k++) sH16[k][lane] = __float2half_rn(h[k]);
        if (lane < I_DIM) {
#pragma unroll
            for (int k = 0; k < NBk; k++) sX16[k][lane] = __float2half_rn(xv[k]);
        }
        __syncwarp();

        // Prefetch next timestep's x (clamped; overlaps gate compute).
        if (lane < I_DIM) {
#pragma unroll
            for (int k = 0; k < NBk; k++) xv[k] = xb[k * XSTRIDE + toff];
        }
        toff = min(toff + I_DIM, XSTRIDE - I_DIM);

        __half2 ai[NBk], af[NBk], ag[NBk], ao[NBk];

        // q = 0 chunk peeled: bias split enters as the HFMA2 addend.
#pragma unroll
        for (int k = 0; k < NBk; k++) {
            U16H r; r.u = *(const uint4*)&sH16[k][0];   // h[0..7] as 4x half2
            ai[k] = __hfma2(whi[0], r.h[0], bp_i);
            af[k] = __hfma2(whf[0], r.h[0], bp_f);
            ag[k] = __hfma2(whg[0], r.h[0], bp_g);
            ao[k] = __hfma2(who[0], r.h[0], bp_o);
#pragma unroll
            for (int j = 1; j < 4; j++) {
                ai[k] = __hfma2(whi[j], r.h[j], ai[k]);
                af[k] = __hfma2(whf[j], r.h[j], af[k]);
                ag[k] = __hfma2(whg[j], r.h[j], ag[k]);
                ao[k] = __hfma2(who[j], r.h[j], ao[k]);
            }
        }
        // Remaining recurrent chunks: q = 1..3 (h[8q .. 8q+7]).
#pragma unroll
        for (int q = 1; q < 4; q++) {
#pragma unroll
            for (int k = 0; k < NBk; k++) {
                U16H r; r.u = *(const uint4*)&sH16[k][8 * q];
#pragma unroll
                for (int j = 0; j < 4; j++) {
                    ai[k] = __hfma2(whi[4 * q + j], r.h[j], ai[k]);
                    af[k] = __hfma2(whf[4 * q + j], r.h[j], af[k]);
                    ag[k] = __hfma2(whg[4 * q + j], r.h[j], ag[k]);
                    ao[k] = __hfma2(who[4 * q + j], r.h[j], ao[k]);
                }
            }
        }
        // Input part: vectorized x reads (LDS.128 + LDS.32 per batch).
        U16H xr[NBk]; __half2 x4[NBk];
#pragma unroll
        for (int k = 0; k < NBk; k++) {
            xr[k].u = *(const uint4*)&sX16[k][0];         // pairs p = 0..3
            x4[k]   = *(const __half2*)&sX16[k][8];       // pair  p = 4
        }
#pragma unroll
        for (int p = 0; p < 4; p++) {
            U16L w; w.u = sWx16[p][lane];   // h[0]=i, h[1]=f, h[2]=g, h[3]=o
#pragma unroll
            for (int k = 0; k < NBk; k++) {
                ai[k] = __hfma2(w.h[0], xr[k].h[p], ai[k]);
                af[k] = __hfma2(w.h[1], xr[k].h[p], af[k]);
                ag[k] = __hfma2(w.h[2], xr[k].h[p], ag[k]);
                ao[k] = __hfma2(w.h[3], xr[k].h[p], ao[k]);
            }
        }
        {
            U16L w; w.u = sWx16[4][lane];
#pragma unroll
            for (int k = 0; k < NBk; k++) {
                ai[k] = __hfma2(w.h[0], x4[k], ai[k]);
                af[k] = __hfma2(w.h[1], x4[k], af[k]);
                ag[k] = __hfma2(w.h[2], x4[k], ag[k]);
                ao[k] = __hfma2(w.h[3], x4[k], ao[k]);
            }
        }

        // Paired activations: one tanh.approx.f16x2 per gate-pair.
        // s_if = (i_e+i_o, f_e+f_o); s_go = (g_e+g_o, o_e+o_o).
#pragma unroll
        for (int k = 0; k < NBk; k++) {
            const __half2 s_if = __hadd2(__lows2half2(ai[k], af[k]),
                                         __highs2half2(ai[k], af[k]));
            const __half2 s_go = __hadd2(__lows2half2(ag[k], ao[k]),
                                         __highs2half2(ag[k], ao[k]));
            const __half2 t_if = tanh2(s_if);            // (tanh(xi/2), tanh(xf/2))
            const __half2 t_go = tanh2(s_go);            // (tanh(xg), tanh(xo/2))
            const __half2 g_if = __hfma2(t_if, k_05_05, k_05_05);  // (sig_i, sig_f)
            const __half2 g_go = __hfma2(t_go, k_10_05, k_00_05);  // (tanh_g, sig_o)
            const float2 vif = __half22float2(g_if);
            const float2 vgo = __half22float2(g_go);
            c[k] = fmaf(vif.y, c[k], vif.x * vgo.x);
            h[k] = vgo.y * tanhm(c[k]);
        }
        __syncwarp();
    }

    // Final dense (fp32): out[b] = sum_l h[b][l] * Wd[l] + bd
    const float wd = Wd[lane];
    const float bdv = bd[0];
#pragma unroll
    for (int k = 0; k < NBk; k++) {
        float p = h[k] * wd;
#pragma unroll
        for (int off = 16; off; off >>= 1)
            p += __shfl_xor_sync(0xffffffffu, p, off);
        if (lane == 0) out[b0 + k] = p + bdv;
    }
}

__global__ __launch_bounds__(32, 8) void lstm_r17_kernel(
    const float* __restrict__ x,    // [B, T, I]
    const float* __restrict__ Wih,  // [4H, I]
    const float* __restrict__ Whh,  // [4H, H]
    const float* __restrict__ bih,  // [4H]
    const float* __restrict__ bhh,  // [4H]
    const float* __restrict__ Wd,   // [1, H]
    const float* __restrict__ bd,   // [1]
    float* __restrict__ out)        // [B, 1]
{
    __shared__ ulonglong2 sWx16[5][32];                 // fp16 x-weights
    __shared__ __align__(16) __half sH16[4][H_DIM];     // fp16 h broadcast
    __shared__ __align__(16) __half sX16[4][16];        // fp16 x broadcast

    const int lane = threadIdx.x;
    const int bid = blockIdx.x;

    // ---- Recurrent weights into registers as fp16x2 j-pairs.
    // i,f,o rows scaled by 0.5 (sigmoid-via-tanh); g row unscaled.
    __half2 whi[16], whf[16], whg[16], who[16];
#pragma unroll
    for (int p = 0; p < 16; p++) {
        const float* r0 = &Whh[(0 * 32 + lane) * H_DIM + 2 * p];
        const float* r1 = &Whh[(1 * 32 + lane) * H_DIM + 2 * p];
        const float* r2 = &Whh[(2 * 32 + lane) * H_DIM + 2 * p];
        const float* r3 = &Whh[(3 * 32 + lane) * H_DIM + 2 * p];
        whi[p] = __floats2half2_rn(SH * r0[0], SH * r0[1]);
        whf[p] = __floats2half2_rn(SH * r1[0], SH * r1[1]);
        whg[p] = __floats2half2_rn(r2[0], r2[1]);
        who[p] = __floats2half2_rn(SH * r3[0], SH * r3[1]);
    }
    // x-weights into smem: per (p, lane) one 16B = 4 gates' __half2 pairs.
#pragma unroll
    for (int p = 0; p < 5; p++) {
        U16L w;
        w.h[0] = __floats2half2_rn(SH * Wih[(0 * 32 + lane) * I_DIM + 2 * p],
                                   SH * Wih[(0 * 32 + lane) * I_DIM + 2 * p + 1]);
        w.h[1] = __floats2half2_rn(SH * Wih[(1 * 32 + lane) * I_DIM + 2 * p],
                                   SH * Wih[(1 * 32 + lane) * I_DIM + 2 * p + 1]);
        w.h[2] = __floats2half2_rn(Wih[(2 * 32 + lane) * I_DIM + 2 * p],
                                   Wih[(2 * 32 + lane) * I_DIM + 2 * p + 1]);
        w.h[3] = __floats2half2_rn(SH * Wih[(3 * 32 + lane) * I_DIM + 2 * p],
                                   SH * Wih[(3 * 32 + lane) * I_DIM + 2 * p + 1]);
        sWx16[p][lane] = w.u;
    }
    // Bias (scaled for sigmoid gates), split across accumulator halves.
    const __half2 bp_i = bias_split(SH * (bih[0 * 32 + lane] + bhh[0 * 32 + lane]));
    const __half2 bp_f = bias_split(SH * (bih[1 * 32 + lane] + bhh[1 * 32 + lane]));
    const __half2 bp_g = bias_split(bih[2 * 32 + lane] + bhh[2 * 32 + lane]);
    const __half2 bp_o = bias_split(SH * (bih[3 * 32 + lane] + bhh[3 * 32 + lane]));
    __syncwarp();

    if (bid < NB4_BLOCKS) {
        lstm_run<4>(lane, 4 * bid,
                    whi, whf, whg, who, bp_i, bp_f, bp_g, bp_o,
                    sWx16, sH16, sX16, x, Wd, bd, out);
    } else {
        lstm_run<3>(lane, NB4_BLOCKS * 4 + 3 * (bid - NB4_BLOCKS),
                    whi, whf, whg, who, bp_i, bp_f, bp_g, bp_o,
                    sWx16, sH16, sX16, x, Wd, bd, out);
    }
}

extern "C" void kernel_launch(void* const* d_in, const int* in_sizes, int n_in,
                              void* d_out, int out_size) {
    const float* x   = (const float*)d_in[0];
    const float* Wih = (const float*)d_in[1];
    const float* Whh = (const float*)d_in[2];
    const float* bih = (const float*)d_in[3];
    const float* bhh = (const float*)d_in[4];
    const float* Wd  = (const float*)d_in[5];
    const float* bd  = (const float*)d_in[6];
    (void)in_sizes; (void)n_in; (void)out_size;

    lstm_r17_kernel<<<GRID_SZ, 32>>>(x, Wih, Whh, bih, bhh, Wd, bd,
                                     (float*)d_out);
}